// round 15
// baseline (speedup 1.0000x reference)
#include <cuda_runtime.h>
#include <cuda_fp16.h>
#include <math.h>
#include <stdint.h>

// Problem dims
#define B_DIM 8192
#define D_DIM 1024
#define H_DIM 4096
#define E_DIM 8
#define C_DIM 1024

// GEMM tiling (fp16 operands, fp32 accum): CTA 128x256, 8 warps of 64x64
#define BM 128
#define BN 256
#define BK 64                            // halves per stage row = 128 B
#define NST 3
#define AS_ST 72                         // halves per A row (64 + 8 pad) -> conflict-free LDSM
#define BS_ST 72                         // halves per B row ([n][k] layout)
#define A_STAGE_BYTES (BM * AS_ST * 2)   // 18432
#define B_STAGE_BYTES (BN * BS_ST * 2)   // 36864
#define STAGE_BYTES (A_STAGE_BYTES + B_STAGE_BYTES)  // 55296
#define SMEM_BYTES (NST * STAGE_BYTES)   // 165888

// Scratch (__device__ globals; allocation-free rule)
__device__ __half g_hbuf[(size_t)B_DIM * E_DIM * H_DIM];  // 512 MB: relu(x@W1+b1) fp16
__device__ __half g_w1t [(size_t)E_DIM * H_DIM * D_DIM];  // 64 MB: W1^T [E][H][D] fp16
__device__ __half g_w2t [(size_t)E_DIM * C_DIM * H_DIM];  // 64 MB: W2^T [E][C][H] fp16
__device__ __half g_xh  [(size_t)B_DIM * D_DIM];          // 16 MB

// ---------------------------------------------------------------------------
// helpers
// ---------------------------------------------------------------------------
__device__ __forceinline__ void cp_async16(const void* smem_dst, const void* gsrc) {
    unsigned s = (unsigned)__cvta_generic_to_shared((void*)smem_dst);
    asm volatile("cp.async.cg.shared.global [%0], [%1], 16;" :: "r"(s), "l"(gsrc));
}

__device__ __forceinline__ void ldsm_x4(uint32_t* r, uint32_t addr) {
    asm volatile("ldmatrix.sync.aligned.m8n8.x4.shared.b16 {%0,%1,%2,%3}, [%4];"
                 : "=r"(r[0]), "=r"(r[1]), "=r"(r[2]), "=r"(r[3]) : "r"(addr));
}

__device__ __forceinline__ void mma_f16(float* c, const uint32_t* a, const uint32_t* b) {
    asm volatile(
        "mma.sync.aligned.m16n8k16.row.col.f32.f16.f16.f32 "
        "{%0,%1,%2,%3}, {%4,%5,%6,%7}, {%8,%9}, {%0,%1,%2,%3};"
        : "+f"(c[0]), "+f"(c[1]), "+f"(c[2]), "+f"(c[3])
        : "r"(a[0]), "r"(a[1]), "r"(a[2]), "r"(a[3]), "r"(b[0]), "r"(b[1]));
}

// ---------------------------------------------------------------------------
// FP16 GEMM (fp32 accum): C = op( A @ Bt^T + bias )
// A:  [M][K] half row-major (lda). Bt: [N][K] half row-major (ldb).
// 256 threads, 8 warps of 64x64. BK=64: ONE sync per 4 k16-chunks.
// 3-stage cp.async (prefetch dist 2), register fragment double-buffer.
// ---------------------------------------------------------------------------
template <bool HOUT>
__global__ void __launch_bounds__(256, 1)
gemm_f16(const __half* __restrict__ A, const __half* __restrict__ Bt,
         const float* __restrict__ bias, void* __restrict__ Cv,
         int K, int lda, int ldb, int ldc,
         long sAe, long sBe, long sBiasE, long sCe)
{
    extern __shared__ __half sm[];

    const int e = blockIdx.z;
    A    += (long)e * sAe;
    Bt   += (long)e * sBe;
    bias += (long)e * sBiasE;

    const int m0 = blockIdx.y * BM;
    const int n0 = blockIdx.x * BN;
    const int tid  = threadIdx.x;
    const int lane = tid & 31;
    const int wid  = tid >> 5;
    const int wm0 = (wid & 1) * 64;   // 2 warps along M
    const int wn0 = (wid >> 1) * 64;  // 4 warps along N
    const int g = lane >> 2, q = lane & 3;

    const uint32_t sm_u32 = (uint32_t)__cvta_generic_to_shared(sm);

    // LDSM per-lane address components
    const int aRow = ((lane >> 3) & 1) * 8 + (lane & 7);   // + mt*16 + wm0
    const int aCol = (lane >> 4) * 8;                      // + kk*16
    // B frags (non-trans, [n][k] tile)
    const int bRowL = (lane & 7) + ((lane >> 4) & 1) * 8;  // + p*16 + wn0
    const int bK    = ((lane >> 3) & 1) * 8;               // + kk*16

    float acc[4][8][4];
#pragma unroll
    for (int mt = 0; mt < 4; mt++)
#pragma unroll
        for (int nt = 0; nt < 8; nt++)
#pragma unroll
            for (int i = 0; i < 4; i++) acc[mt][nt][i] = 0.f;

    auto load_tile = [&](int kb, int s) {
        __half* as = sm + s * (STAGE_BYTES / 2);
        __half* bs = as + A_STAGE_BYTES / 2;
#pragma unroll
        for (int i = 0; i < 4; i++) {            // A: 128 rows x 8 chunks(16B)
            int lin = tid + i * 256;
            int row = lin >> 3, c8 = (lin & 7) << 3;
            cp_async16(&as[row * AS_ST + c8], &A[(long)(m0 + row) * lda + kb + c8]);
        }
#pragma unroll
        for (int i = 0; i < 8; i++) {            // B: 256 rows x 8 chunks(16B)
            int lin = tid + i * 256;
            int row = lin >> 3, c8 = (lin & 7) << 3;
            cp_async16(&bs[row * BS_ST + c8], &Bt[(long)(n0 + row) * ldb + kb + c8]);
        }
        asm volatile("cp.async.commit_group;" ::: "memory");
    };

    // fragment load for k16-chunk kk (0..3) from stage s via ldmatrix
    auto load_frag = [&](int kk, int s, uint32_t af[4][4], uint32_t bf[8][2]) {
        uint32_t sa = sm_u32 + s * STAGE_BYTES;
        uint32_t sb = sa + A_STAGE_BYTES;
#pragma unroll
        for (int mt = 0; mt < 4; mt++)
            ldsm_x4(af[mt], sa + ((wm0 + mt * 16 + aRow) * AS_ST + kk * 16 + aCol) * 2);
#pragma unroll
        for (int p = 0; p < 4; p++) {
            uint32_t r[4];
            ldsm_x4(r, sb + ((wn0 + p * 16 + bRowL) * BS_ST + kk * 16 + bK) * 2);
            bf[2 * p][0] = r[0]; bf[2 * p][1] = r[1];
            bf[2 * p + 1][0] = r[2]; bf[2 * p + 1][1] = r[3];
        }
    };

    const int KT = K / BK;   // 16 (GEMM1) or 64 (GEMM2)

    // prologue: 2 stages in flight, stage 0 resident, frag chunk 0 in regs
    load_tile(0, 0);
    load_tile(BK, 1);
    asm volatile("cp.async.wait_group 1;" ::: "memory");
    __syncthreads();

    uint32_t a[2][4][4], b[2][8][2];
    load_frag(0, 0, a[0], b[0]);

    for (int kt = 0; kt < KT; kt++) {
        const int cur = kt % NST;
#pragma unroll
        for (int kk = 0; kk < 4; kk++) {         // four k16 chunks per BK=64 stage
            const int cb = kk & 1, nb = cb ^ 1;
            if (kk == 3) {
                asm volatile("cp.async.wait_group 1;" ::: "memory");
                __syncthreads();
                if (kt + 1 < KT)
                    load_frag(0, (kt + 1) % NST, a[nb], b[nb]);
            } else {
                load_frag(kk + 1, cur, a[nb], b[nb]);
                if (kk == 0) {
                    if (kt + 2 < KT) load_tile((kt + 2) * BK, (kt + 2) % NST);
                    else asm volatile("cp.async.commit_group;" ::: "memory");
                }
            }
#pragma unroll
            for (int mt = 0; mt < 4; mt++)
#pragma unroll
                for (int nt = 0; nt < 8; nt++)
                    mma_f16(acc[mt][nt], a[cb][mt], b[cb][nt]);
        }
    }

    // Epilogue
#pragma unroll
    for (int mt = 0; mt < 4; mt++) {
        int r = m0 + wm0 + mt * 16 + g;
#pragma unroll
        for (int nt = 0; nt < 8; nt++) {
            int c = n0 + wn0 + nt * 8 + 2 * q;
            float b0v = bias[c], b1v = bias[c + 1];
            float v00 = acc[mt][nt][0] + b0v;
            float v01 = acc[mt][nt][1] + b1v;
            float v10 = acc[mt][nt][2] + b0v;
            float v11 = acc[mt][nt][3] + b1v;
            if (HOUT) {
                __half* C = (__half*)Cv + (long)e * sCe;
                __half2 h0 = __floats2half2_rn(fmaxf(v00, 0.f), fmaxf(v01, 0.f));
                __half2 h1 = __floats2half2_rn(fmaxf(v10, 0.f), fmaxf(v11, 0.f));
                *(__half2*)&C[(long)r * ldc + c]       = h0;
                *(__half2*)&C[(long)(r + 8) * ldc + c] = h1;
            } else {
                float* C = (float*)Cv + (long)e * sCe;
                C[(long)r * ldc + c]           = v00;
                C[(long)r * ldc + c + 1]       = v01;
                C[(long)(r + 8) * ldc + c]     = v10;
                C[(long)(r + 8) * ldc + c + 1] = v11;
            }
        }
    }
}

// ---------------------------------------------------------------------------
// Pre-pass: out[e][n][k] = fp16(in[e][k][n])  (tiled transpose + convert)
// ---------------------------------------------------------------------------
__global__ void f2h_transpose(const float* __restrict__ in, __half* __restrict__ out,
                              int Kd, int Nd)
{
    __shared__ float t[32][33];
    int e = blockIdx.z;
    in  += (long)e * Kd * Nd;
    out += (long)e * Kd * Nd;
    int k0 = blockIdx.y * 32, n0 = blockIdx.x * 32;
    int tx = threadIdx.x, ty = threadIdx.y;   // 32 x 8
#pragma unroll
    for (int i = 0; i < 32; i += 8)
        t[ty + i][tx] = in[(long)(k0 + ty + i) * Nd + n0 + tx];
    __syncthreads();
#pragma unroll
    for (int i = 0; i < 32; i += 8)
        out[(long)(n0 + ty + i) * Kd + k0 + tx] = __float2half_rn(t[tx][ty + i]);
}

// Pre-pass: fp32 -> fp16 (RNE), n multiple of 1024
__global__ void f2h_copy(const float* __restrict__ in, __half* __restrict__ out)
{
    long i = ((long)blockIdx.x * 256 + threadIdx.x) * 4;
    float4 v = *(const float4*)&in[i];
    __half2 h0 = __floats2half2_rn(v.x, v.y);
    __half2 h1 = __floats2half2_rn(v.z, v.w);
    uint2 u;
    u.x = *reinterpret_cast<unsigned*>(&h0);
    u.y = *reinterpret_cast<unsigned*>(&h1);
    *(uint2*)(out + i) = u;
}

// ---------------------------------------------------------------------------
// Gating: softmax(x @ Wg + bg). One warp per row (fp32 exact).
// ---------------------------------------------------------------------------
__global__ void gating_kernel(const float* __restrict__ x, const float* __restrict__ Wg,
                              const float* __restrict__ bg, float* __restrict__ gate)
{
    int warp = threadIdx.x >> 5, lane = threadIdx.x & 31;
    int b = blockIdx.x * 8 + warp;
    const float* xr = x + (long)b * D_DIM;

    float acc[8];
#pragma unroll
    for (int i = 0; i < 8; i++) acc[i] = 0.f;

    for (int d = lane; d < D_DIM; d += 32) {
        float xv = xr[d];
        const float4* w = reinterpret_cast<const float4*>(Wg + (long)d * E_DIM);
        float4 w0 = w[0], w1 = w[1];
        acc[0] += xv * w0.x; acc[1] += xv * w0.y;
        acc[2] += xv * w0.z; acc[3] += xv * w0.w;
        acc[4] += xv * w1.x; acc[5] += xv * w1.y;
        acc[6] += xv * w1.z; acc[7] += xv * w1.w;
    }
#pragma unroll
    for (int off = 16; off > 0; off >>= 1)
#pragma unroll
        for (int i = 0; i < 8; i++)
            acc[i] += __shfl_xor_sync(0xffffffffu, acc[i], off);

    if (lane == 0) {
        float m = -1e30f;
#pragma unroll
        for (int i = 0; i < 8; i++) { acc[i] += bg[i]; m = fmaxf(m, acc[i]); }
        float s = 0.f;
#pragma unroll
        for (int i = 0; i < 8; i++) { acc[i] = expf(acc[i] - m); s += acc[i]; }
        float inv = 1.f / s;
#pragma unroll
        for (int i = 0; i < 8; i++) gate[(long)b * 8 + i] = acc[i] * inv;
    }
}

// ---------------------------------------------------------------------------
// Mixture: mix[b][c] = sum_e gate[b][e] * eo[b][e][c]
// ---------------------------------------------------------------------------
__global__ void mixture_kernel(const float* __restrict__ gate, const float* __restrict__ eo,
                               float* __restrict__ mix)
{
    int b = blockIdx.x;
    __shared__ float gs[8];
    if (threadIdx.x < 8) gs[threadIdx.x] = gate[(long)b * 8 + threadIdx.x];
    __syncthreads();

    int c4 = threadIdx.x;
    const float4* eob = reinterpret_cast<const float4*>(eo + (long)b * E_DIM * C_DIM);
    float4 a = make_float4(0.f, 0.f, 0.f, 0.f);
#pragma unroll
    for (int e = 0; e < 8; e++) {
        float4 v = eob[e * (C_DIM / 4) + c4];
        float ge = gs[e];
        a.x += ge * v.x; a.y += ge * v.y; a.z += ge * v.z; a.w += ge * v.w;
    }
    reinterpret_cast<float4*>(mix + (long)b * C_DIM)[c4] = a;
}

// ---------------------------------------------------------------------------
// kernel_launch
// ---------------------------------------------------------------------------
extern "C" void kernel_launch(void* const* d_in, const int* in_sizes, int n_in,
                              void* d_out, int out_size)
{
    const float* x  = (const float*)d_in[0];
    const float* W1 = (const float*)d_in[1];
    const float* b1 = (const float*)d_in[2];
    const float* W2 = (const float*)d_in[3];
    const float* b2 = (const float*)d_in[4];
    const float* Wg = (const float*)d_in[5];
    const float* bg = (const float*)d_in[6];

    // Output layout: mixture [B,C] | gating [B,E] | expert_outputs [B,E,C]
    float* out  = (float*)d_out;
    float* mix  = out;
    float* gate = out + (size_t)B_DIM * C_DIM;
    float* eo   = gate + (size_t)B_DIM * E_DIM;

    __half *hbuf, *w1t, *w2t, *xh;
    cudaGetSymbolAddress((void**)&hbuf, g_hbuf);
    cudaGetSymbolAddress((void**)&w1t,  g_w1t);
    cudaGetSymbolAddress((void**)&w2t,  g_w2t);
    cudaGetSymbolAddress((void**)&xh,   g_xh);

    cudaFuncSetAttribute(gemm_f16<true>,  cudaFuncAttributeMaxDynamicSharedMemorySize, SMEM_BYTES);
    cudaFuncSetAttribute(gemm_f16<false>, cudaFuncAttributeMaxDynamicSharedMemorySize, SMEM_BYTES);

    // gating (fp32 exact, independent)
    gating_kernel<<<B_DIM / 8, 256>>>(x, Wg, bg, gate);

    // pre-pass: x -> fp16; W1, W2 -> transposed fp16 [E][N][K]
    f2h_copy<<<((long)B_DIM * D_DIM) / 1024, 256>>>(x, xh);
    f2h_transpose<<<dim3(H_DIM / 32, D_DIM / 32, E_DIM), dim3(32, 8)>>>(W1, w1t, D_DIM, H_DIM);
    f2h_transpose<<<dim3(C_DIM / 32, H_DIM / 32, E_DIM), dim3(32, 8)>>>(W2, w2t, H_DIM, C_DIM);

    // GEMM1: hbuf = fp16(relu(x @ W1[e] + b1[e]))  [B][E][H]
    dim3 g1(H_DIM / BN, B_DIM / BM, E_DIM);
    gemm_f16<true><<<g1, 256, SMEM_BYTES>>>(
        xh, w1t, b1, hbuf,
        /*K=*/D_DIM, /*lda=*/D_DIM, /*ldb=*/D_DIM, /*ldc=*/E_DIM * H_DIM,
        /*sAe=*/0L, /*sBe=*/(long)H_DIM * D_DIM, /*sBiasE=*/(long)H_DIM, /*sCe=*/(long)H_DIM);

    // GEMM2: eo[:,e,:] = h_e @ W2[e] + b2[e]  (fp32 store)
    dim3 g2(C_DIM / BN, B_DIM / BM, E_DIM);
    gemm_f16<false><<<g2, 256, SMEM_BYTES>>>(
        hbuf, w2t, b2, eo,
        /*K=*/H_DIM, /*lda=*/E_DIM * H_DIM, /*ldb=*/H_DIM, /*ldc=*/E_DIM * C_DIM,
        /*sAe=*/(long)H_DIM, /*sBe=*/(long)C_DIM * H_DIM, /*sBiasE=*/(long)C_DIM, /*sCe=*/(long)C_DIM);

    // mixture
    mixture_kernel<<<B_DIM, 256>>>(gate, eo, mix);
}

// round 16
// speedup vs baseline: 1.0871x; 1.0871x over previous
#include <cuda_runtime.h>
#include <cuda_fp16.h>
#include <math.h>
#include <stdint.h>

// Problem dims
#define B_DIM 8192
#define D_DIM 1024
#define H_DIM 4096
#define E_DIM 8
#define C_DIM 1024

// GEMM tiling (fp16 operands, fp32 accum): CTA 128x256, 8 warps of 64x64
#define BM 128
#define BN 256
#define BK 32
#define NST 4
#define AS_ST 40                         // halves per A row (32 + 8 pad)
#define BS_ST 40                         // halves per B row ([n][k] layout, 32 + 8 pad)
#define A_STAGE_BYTES (BM * AS_ST * 2)   // 10240
#define B_STAGE_BYTES (BN * BS_ST * 2)   // 20480
#define STAGE_BYTES (A_STAGE_BYTES + B_STAGE_BYTES)  // 30720
#define SMEM_BYTES (NST * STAGE_BYTES)   // 122880

// Scratch (__device__ globals; allocation-free rule)
__device__ __half g_hbuf[(size_t)B_DIM * E_DIM * H_DIM];  // 512 MB: relu(x@W1+b1) fp16
__device__ __half g_w1t [(size_t)E_DIM * H_DIM * D_DIM];  // 64 MB: W1^T [E][H][D] fp16
__device__ __half g_w2t [(size_t)E_DIM * C_DIM * H_DIM];  // 64 MB: W2^T [E][C][H] fp16
__device__ __half g_xh  [(size_t)B_DIM * D_DIM];          // 16 MB

// ---------------------------------------------------------------------------
// helpers
// ---------------------------------------------------------------------------
__device__ __forceinline__ void cp_async16(const void* smem_dst, const void* gsrc) {
    unsigned s = (unsigned)__cvta_generic_to_shared((void*)smem_dst);
    asm volatile("cp.async.cg.shared.global [%0], [%1], 16;" :: "r"(s), "l"(gsrc));
}

__device__ __forceinline__ void ldsm_x4(uint32_t* r, uint32_t addr) {
    asm volatile("ldmatrix.sync.aligned.m8n8.x4.shared.b16 {%0,%1,%2,%3}, [%4];"
                 : "=r"(r[0]), "=r"(r[1]), "=r"(r[2]), "=r"(r[3]) : "r"(addr));
}

__device__ __forceinline__ void mma_f16(float* c, const uint32_t* a, const uint32_t* b) {
    asm volatile(
        "mma.sync.aligned.m16n8k16.row.col.f32.f16.f16.f32 "
        "{%0,%1,%2,%3}, {%4,%5,%6,%7}, {%8,%9}, {%0,%1,%2,%3};"
        : "+f"(c[0]), "+f"(c[1]), "+f"(c[2]), "+f"(c[3])
        : "r"(a[0]), "r"(a[1]), "r"(a[2]), "r"(a[3]), "r"(b[0]), "r"(b[1]));
}

// ---------------------------------------------------------------------------
// FP16 GEMM (fp32 accum): C = op( A @ Bt^T + bias )   [R14 configuration]
// A:  [M][K] half row-major (lda). Bt: [N][K] half row-major (ldb).
// 256 threads, 8 warps of 64x64. 4-stage cp.async (prefetch dist 3),
// 1 sync/tile, non-trans ldmatrix for both operands, reg double-buffer.
// ---------------------------------------------------------------------------
template <bool HOUT>
__global__ void __launch_bounds__(256, 1)
gemm_f16(const __half* __restrict__ A, const __half* __restrict__ Bt,
         const float* __restrict__ bias, void* __restrict__ Cv,
         int K, int lda, int ldb, int ldc,
         long sAe, long sBe, long sBiasE, long sCe)
{
    extern __shared__ __half sm[];

    const int e = blockIdx.z;
    A    += (long)e * sAe;
    Bt   += (long)e * sBe;
    bias += (long)e * sBiasE;

    const int m0 = blockIdx.y * BM;
    const int n0 = blockIdx.x * BN;
    const int tid  = threadIdx.x;
    const int lane = tid & 31;
    const int wid  = tid >> 5;
    const int wm0 = (wid & 1) * 64;   // 2 warps along M
    const int wn0 = (wid >> 1) * 64;  // 4 warps along N
    const int g = lane >> 2, q = lane & 3;

    const uint32_t sm_u32 = (uint32_t)__cvta_generic_to_shared(sm);

    const int aRow = ((lane >> 3) & 1) * 8 + (lane & 7);   // + mt*16 + wm0
    const int aCol = (lane >> 4) * 8;                      // + kk*16
    const int bRowL = (lane & 7) + ((lane >> 4) & 1) * 8;  // + p*16 + wn0
    const int bK    = ((lane >> 3) & 1) * 8;               // + kk*16

    float acc[4][8][4];
#pragma unroll
    for (int mt = 0; mt < 4; mt++)
#pragma unroll
        for (int nt = 0; nt < 8; nt++)
#pragma unroll
            for (int i = 0; i < 4; i++) acc[mt][nt][i] = 0.f;

    auto load_tile = [&](int kb, int s) {
        __half* as = sm + s * (STAGE_BYTES / 2);
        __half* bs = as + A_STAGE_BYTES / 2;
#pragma unroll
        for (int i = 0; i < 2; i++) {            // A: 128 rows x 4 chunks(16B)
            int lin = tid + i * 256;
            int row = lin >> 2, c8 = (lin & 3) << 3;
            cp_async16(&as[row * AS_ST + c8], &A[(long)(m0 + row) * lda + kb + c8]);
        }
#pragma unroll
        for (int i = 0; i < 4; i++) {            // B: 256 rows x 4 chunks(16B)
            int lin = tid + i * 256;
            int row = lin >> 2, c8 = (lin & 3) << 3;
            cp_async16(&bs[row * BS_ST + c8], &Bt[(long)(n0 + row) * ldb + kb + c8]);
        }
        asm volatile("cp.async.commit_group;" ::: "memory");
    };

    auto load_frag = [&](int kk, int s, uint32_t af[4][4], uint32_t bf[8][2]) {
        uint32_t sa = sm_u32 + s * STAGE_BYTES;
        uint32_t sb = sa + A_STAGE_BYTES;
#pragma unroll
        for (int mt = 0; mt < 4; mt++)
            ldsm_x4(af[mt], sa + ((wm0 + mt * 16 + aRow) * AS_ST + kk * 16 + aCol) * 2);
#pragma unroll
        for (int p = 0; p < 4; p++) {
            uint32_t r[4];
            ldsm_x4(r, sb + ((wn0 + p * 16 + bRowL) * BS_ST + kk * 16 + bK) * 2);
            bf[2 * p][0] = r[0]; bf[2 * p][1] = r[1];
            bf[2 * p + 1][0] = r[2]; bf[2 * p + 1][1] = r[3];
        }
    };

    const int KT = K / BK;   // 32 (GEMM1) or 128 (GEMM2)

    // prologue: 3 stages in flight
    load_tile(0, 0);
    load_tile(BK, 1);
    load_tile(2 * BK, 2);
    asm volatile("cp.async.wait_group 2;" ::: "memory");
    __syncthreads();

    uint32_t a[2][4][4], b[2][8][2];
    load_frag(0, 0, a[0], b[0]);

    for (int kt = 0; kt < KT; kt++) {
        const int cur = kt & (NST - 1);
#pragma unroll
        for (int kk = 0; kk < 2; kk++) {         // two k16 chunks per BK=32 stage
            const int cb = kk & 1, nb = cb ^ 1;
            if (kk == 1) {
                asm volatile("cp.async.wait_group 2;" ::: "memory");
                __syncthreads();
                if (kt + 1 < KT)
                    load_frag(0, (kt + 1) & (NST - 1), a[nb], b[nb]);
            } else {
                load_frag(1, cur, a[nb], b[nb]);
                if (kt + 3 < KT) load_tile((kt + 3) * BK, (kt + 3) & (NST - 1));
                else asm volatile("cp.async.commit_group;" ::: "memory");
            }
#pragma unroll
            for (int mt = 0; mt < 4; mt++)
#pragma unroll
                for (int nt = 0; nt < 8; nt++)
                    mma_f16(acc[mt][nt], a[cb][mt], b[cb][nt]);
        }
    }

    // Epilogue
#pragma unroll
    for (int mt = 0; mt < 4; mt++) {
        int r = m0 + wm0 + mt * 16 + g;
#pragma unroll
        for (int nt = 0; nt < 8; nt++) {
            int c = n0 + wn0 + nt * 8 + 2 * q;
            float b0v = bias[c], b1v = bias[c + 1];
            float v00 = acc[mt][nt][0] + b0v;
            float v01 = acc[mt][nt][1] + b1v;
            float v10 = acc[mt][nt][2] + b0v;
            float v11 = acc[mt][nt][3] + b1v;
            if (HOUT) {
                __half* C = (__half*)Cv + (long)e * sCe;
                __half2 h0 = __floats2half2_rn(fmaxf(v00, 0.f), fmaxf(v01, 0.f));
                __half2 h1 = __floats2half2_rn(fmaxf(v10, 0.f), fmaxf(v11, 0.f));
                *(__half2*)&C[(long)r * ldc + c]       = h0;
                *(__half2*)&C[(long)(r + 8) * ldc + c] = h1;
            } else {
                float* C = (float*)Cv + (long)e * sCe;
                C[(long)r * ldc + c]           = v00;
                C[(long)r * ldc + c + 1]       = v01;
                C[(long)(r + 8) * ldc + c]     = v10;
                C[(long)(r + 8) * ldc + c + 1] = v11;
            }
        }
    }
}

// ---------------------------------------------------------------------------
// Pre-pass: out[e][n][k] = fp16(in[e][k][n])
// 64(k) x 32(n) tile per block; n-major smem; half2 contiguous stores.
// ---------------------------------------------------------------------------
__global__ void f2h_transpose(const float* __restrict__ in, __half* __restrict__ out,
                              int Kd, int Nd)
{
    __shared__ float t[32][65];               // [n_local][k_local], +1 col pad
    int e = blockIdx.z;
    in  += (long)e * Kd * Nd;
    out += (long)e * Kd * Nd;
    int n0 = blockIdx.x * 32, k0 = blockIdx.y * 64;
    int tx = threadIdx.x, ty = threadIdx.y;   // 32 x 8
#pragma unroll
    for (int kk = 0; kk < 64; kk += 8)        // coalesced fp32 loads, cf stores
        t[tx][ty + kk] = in[(long)(k0 + ty + kk) * Nd + n0 + tx];
    __syncthreads();
#pragma unroll
    for (int i = 0; i < 32; i += 8) {         // half2 stores: 128B/warp contiguous
        int nl = ty + i;
        __half2 h = __floats2half2_rn(t[nl][2 * tx], t[nl][2 * tx + 1]);
        *(__half2*)&out[(long)(n0 + nl) * Kd + k0 + 2 * tx] = h;
    }
}

// ---------------------------------------------------------------------------
// Gating + x->fp16: softmax(x @ Wg + bg); also writes xh = fp16(x).
// One warp per row (fp32 exact dot products).
// ---------------------------------------------------------------------------
__global__ void gating_kernel(const float* __restrict__ x, const float* __restrict__ Wg,
                              const float* __restrict__ bg, float* __restrict__ gate,
                              __half* __restrict__ xh)
{
    int warp = threadIdx.x >> 5, lane = threadIdx.x & 31;
    int b = blockIdx.x * 8 + warp;
    const float* xr = x + (long)b * D_DIM;
    __half* xo = xh + (long)b * D_DIM;

    float acc[8];
#pragma unroll
    for (int i = 0; i < 8; i++) acc[i] = 0.f;

    for (int d = lane; d < D_DIM; d += 32) {
        float xv = xr[d];
        xo[d] = __float2half_rn(xv);          // fused fp16 conversion of x
        const float4* w = reinterpret_cast<const float4*>(Wg + (long)d * E_DIM);
        float4 w0 = w[0], w1 = w[1];
        acc[0] += xv * w0.x; acc[1] += xv * w0.y;
        acc[2] += xv * w0.z; acc[3] += xv * w0.w;
        acc[4] += xv * w1.x; acc[5] += xv * w1.y;
        acc[6] += xv * w1.z; acc[7] += xv * w1.w;
    }
#pragma unroll
    for (int off = 16; off > 0; off >>= 1)
#pragma unroll
        for (int i = 0; i < 8; i++)
            acc[i] += __shfl_xor_sync(0xffffffffu, acc[i], off);

    if (lane == 0) {
        float m = -1e30f;
#pragma unroll
        for (int i = 0; i < 8; i++) { acc[i] += bg[i]; m = fmaxf(m, acc[i]); }
        float s = 0.f;
#pragma unroll
        for (int i = 0; i < 8; i++) { acc[i] = expf(acc[i] - m); s += acc[i]; }
        float inv = 1.f / s;
#pragma unroll
        for (int i = 0; i < 8; i++) gate[(long)b * 8 + i] = acc[i] * inv;
    }
}

// ---------------------------------------------------------------------------
// Mixture: mix[b][c] = sum_e gate[b][e] * eo[b][e][c]
// ---------------------------------------------------------------------------
__global__ void mixture_kernel(const float* __restrict__ gate, const float* __restrict__ eo,
                               float* __restrict__ mix)
{
    int b = blockIdx.x;
    __shared__ float gs[8];
    if (threadIdx.x < 8) gs[threadIdx.x] = gate[(long)b * 8 + threadIdx.x];
    __syncthreads();

    int c4 = threadIdx.x;
    const float4* eob = reinterpret_cast<const float4*>(eo + (long)b * E_DIM * C_DIM);
    float4 a = make_float4(0.f, 0.f, 0.f, 0.f);
#pragma unroll
    for (int e = 0; e < 8; e++) {
        float4 v = eob[e * (C_DIM / 4) + c4];
        float ge = gs[e];
        a.x += ge * v.x; a.y += ge * v.y; a.z += ge * v.z; a.w += ge * v.w;
    }
    reinterpret_cast<float4*>(mix + (long)b * C_DIM)[c4] = a;
}

// ---------------------------------------------------------------------------
// kernel_launch
// ---------------------------------------------------------------------------
extern "C" void kernel_launch(void* const* d_in, const int* in_sizes, int n_in,
                              void* d_out, int out_size)
{
    const float* x  = (const float*)d_in[0];
    const float* W1 = (const float*)d_in[1];
    const float* b1 = (const float*)d_in[2];
    const float* W2 = (const float*)d_in[3];
    const float* b2 = (const float*)d_in[4];
    const float* Wg = (const float*)d_in[5];
    const float* bg = (const float*)d_in[6];

    // Output layout: mixture [B,C] | gating [B,E] | expert_outputs [B,E,C]
    float* out  = (float*)d_out;
    float* mix  = out;
    float* gate = out + (size_t)B_DIM * C_DIM;
    float* eo   = gate + (size_t)B_DIM * E_DIM;

    __half *hbuf, *w1t, *w2t, *xh;
    cudaGetSymbolAddress((void**)&hbuf, g_hbuf);
    cudaGetSymbolAddress((void**)&w1t,  g_w1t);
    cudaGetSymbolAddress((void**)&w2t,  g_w2t);
    cudaGetSymbolAddress((void**)&xh,   g_xh);

    cudaFuncSetAttribute(gemm_f16<true>,  cudaFuncAttributeMaxDynamicSharedMemorySize, SMEM_BYTES);
    cudaFuncSetAttribute(gemm_f16<false>, cudaFuncAttributeMaxDynamicSharedMemorySize, SMEM_BYTES);

    // gating + x->fp16 (fused)
    gating_kernel<<<B_DIM / 8, 256>>>(x, Wg, bg, gate, xh);

    // weight transposes -> [E][N][K] fp16
    f2h_transpose<<<dim3(H_DIM / 32, D_DIM / 64, E_DIM), dim3(32, 8)>>>(W1, w1t, D_DIM, H_DIM);
    f2h_transpose<<<dim3(C_DIM / 32, H_DIM / 64, E_DIM), dim3(32, 8)>>>(W2, w2t, H_DIM, C_DIM);

    // GEMM1: hbuf = fp16(relu(x @ W1[e] + b1[e]))  [B][E][H]
    dim3 g1(H_DIM / BN, B_DIM / BM, E_DIM);
    gemm_f16<true><<<g1, 256, SMEM_BYTES>>>(
        xh, w1t, b1, hbuf,
        /*K=*/D_DIM, /*lda=*/D_DIM, /*ldb=*/D_DIM, /*ldc=*/E_DIM * H_DIM,
        /*sAe=*/0L, /*sBe=*/(long)H_DIM * D_DIM, /*sBiasE=*/(long)H_DIM, /*sCe=*/(long)H_DIM);

    // GEMM2: eo[:,e,:] = h_e @ W2[e] + b2[e]  (fp32 store)
    dim3 g2(C_DIM / BN, B_DIM / BM, E_DIM);
    gemm_f16<false><<<g2, 256, SMEM_BYTES>>>(
        hbuf, w2t, b2, eo,
        /*K=*/H_DIM, /*lda=*/E_DIM * H_DIM, /*ldb=*/H_DIM, /*ldc=*/E_DIM * C_DIM,
        /*sAe=*/(long)H_DIM, /*sBe=*/(long)C_DIM * H_DIM, /*sBiasE=*/(long)C_DIM, /*sCe=*/(long)C_DIM);

    // mixture
    mixture_kernel<<<B_DIM, 256>>>(gate, eo, mix);
}